// round 1
// baseline (speedup 1.0000x reference)
#include <cuda_runtime.h>
#include <cstdint>
#include <cstddef>

#define SEQ 256
#define BATCH 32
#define IN_DIM 1024
#define HID 64
#define NM 8
#define NM1 9
#define ROWS (SEQ * BATCH)   /* 8192 */
#define NKV (NM1 * HID)      /* 576  */

// ---------------- scratch (device globals; no allocation allowed) ----------------
__device__ float  g_Ck[(size_t)ROWS * NKV];
__device__ float  g_Cv[(size_t)ROWS * NKV];
__device__ float  g_Cq[(size_t)ROWS * HID];
__device__ int2   g_ri[ROWS];
__device__ float2 g_rg[ROWS];
__device__ float  g_contrib[(size_t)ROWS * NKV];

// ---------------- tf32 mma helpers ----------------
__device__ __forceinline__ uint32_t f2tf(float f) {
    uint32_t u;
    asm("cvt.rna.tf32.f32 %0, %1;" : "=r"(u) : "f"(f));
    return u;
}

__device__ __forceinline__ void mma_tf32(float* d, const uint32_t* a, const uint32_t* b) {
    asm volatile(
        "mma.sync.aligned.m16n8k8.row.col.f32.tf32.tf32.f32 "
        "{%0,%1,%2,%3},{%4,%5,%6,%7},{%8,%9},{%0,%1,%2,%3};"
        : "+f"(d[0]), "+f"(d[1]), "+f"(d[2]), "+f"(d[3])
        : "r"(a[0]), "r"(a[1]), "r"(a[2]), "r"(a[3]), "r"(b[0]), "r"(b[1]));
}

// ---------------- GEMM: C[m,n] = sum_k A[m,k]*B[n,k] + bias[n] ----------------
// A: (M x 1024) row-major, B: (N x 1024) row-major (== col-major k x n for mma).
// CTA tile 64x64, BK=16, 128 threads (4 warps, 2x2 warp grid, 32x32 per warp).
__global__ __launch_bounds__(128) void gemm_tf32(
    const float* __restrict__ A, const float* __restrict__ B,
    const float* __restrict__ bias, float* __restrict__ C, int N)
{
    __shared__ float As[64][17];
    __shared__ float Bs[64][17];

    const int tid  = threadIdx.x;
    const int lane = tid & 31;
    const int warp = tid >> 5;
    const int wm = (warp >> 1) * 32;
    const int wn = (warp & 1) * 32;
    const int lr = tid >> 2;        // 0..31
    const int lc = (tid & 3) * 4;   // 0,4,8,12
    const int m0 = blockIdx.y * 64;
    const int n0 = blockIdx.x * 64;

    float acc[2][4][4];
#pragma unroll
    for (int mt = 0; mt < 2; mt++)
#pragma unroll
        for (int nt = 0; nt < 4; nt++)
#pragma unroll
            for (int i = 0; i < 4; i++) acc[mt][nt][i] = 0.f;

    const float* Ap = A + (size_t)(m0 + lr) * IN_DIM + lc;
    const float* Bp = B + (size_t)(n0 + lr) * IN_DIM + lc;

    for (int k0 = 0; k0 < IN_DIM; k0 += 16) {
        float4 av0 = *(const float4*)(Ap + k0);
        float4 av1 = *(const float4*)(Ap + (size_t)32 * IN_DIM + k0);
        float4 bv0 = *(const float4*)(Bp + k0);
        float4 bv1 = *(const float4*)(Bp + (size_t)32 * IN_DIM + k0);
        __syncthreads();
        As[lr][lc + 0] = av0.x; As[lr][lc + 1] = av0.y;
        As[lr][lc + 2] = av0.z; As[lr][lc + 3] = av0.w;
        As[lr + 32][lc + 0] = av1.x; As[lr + 32][lc + 1] = av1.y;
        As[lr + 32][lc + 2] = av1.z; As[lr + 32][lc + 3] = av1.w;
        Bs[lr][lc + 0] = bv0.x; Bs[lr][lc + 1] = bv0.y;
        Bs[lr][lc + 2] = bv0.z; Bs[lr][lc + 3] = bv0.w;
        Bs[lr + 32][lc + 0] = bv1.x; Bs[lr + 32][lc + 1] = bv1.y;
        Bs[lr + 32][lc + 2] = bv1.z; Bs[lr + 32][lc + 3] = bv1.w;
        __syncthreads();

#pragma unroll
        for (int ks = 0; ks < 2; ks++) {
            const int kk = ks * 8 + (lane & 3);
            uint32_t af[2][4], bf[4][2];
#pragma unroll
            for (int mt = 0; mt < 2; mt++) {
                const int rr = wm + mt * 16 + (lane >> 2);
                af[mt][0] = f2tf(As[rr][kk]);
                af[mt][1] = f2tf(As[rr + 8][kk]);
                af[mt][2] = f2tf(As[rr][kk + 4]);
                af[mt][3] = f2tf(As[rr + 8][kk + 4]);
            }
#pragma unroll
            for (int nt = 0; nt < 4; nt++) {
                const int nn = wn + nt * 8 + (lane >> 2);
                bf[nt][0] = f2tf(Bs[nn][kk]);
                bf[nt][1] = f2tf(Bs[nn][kk + 4]);
            }
#pragma unroll
            for (int mt = 0; mt < 2; mt++)
#pragma unroll
                for (int nt = 0; nt < 4; nt++)
                    mma_tf32(acc[mt][nt], af[mt], bf[nt]);
        }
    }

#pragma unroll
    for (int mt = 0; mt < 2; mt++)
#pragma unroll
        for (int nt = 0; nt < 4; nt++) {
            const int row = m0 + wm + mt * 16 + (lane >> 2);
            const int col = n0 + wn + nt * 8 + (lane & 3) * 2;
            const float b0 = bias[col], b1 = bias[col + 1];
            C[(size_t)row * N + col]           = acc[mt][nt][0] + b0;
            C[(size_t)row * N + col + 1]       = acc[mt][nt][1] + b1;
            C[(size_t)(row + 8) * N + col]     = acc[mt][nt][2] + b0;
            C[(size_t)(row + 8) * N + col + 1] = acc[mt][nt][3] + b1;
        }
}

// ---------------- gating: exact fp32 logits + softmax + stable top-2 ----------------
// One warp per (t,b) row.
__global__ __launch_bounds__(256) void gate_kernel(
    const float* __restrict__ X, const float* __restrict__ Wg,
    const float* __restrict__ Wgb)
{
    const int wid  = blockIdx.x * 8 + (threadIdx.x >> 5);
    const int lane = threadIdx.x & 31;
    const float4* x4 = (const float4*)(X + (size_t)wid * IN_DIM);
    const float4* w4 = (const float4*)Wg;

    float acc[NM];
#pragma unroll
    for (int n = 0; n < NM; n++) acc[n] = 0.f;

#pragma unroll
    for (int c = 0; c < 8; c++) {
        const float4 xv = x4[c * 32 + lane];
#pragma unroll
        for (int n = 0; n < NM; n++) {
            const float4 wv = w4[n * 256 + c * 32 + lane];
            acc[n] += xv.x * wv.x + xv.y * wv.y + xv.z * wv.z + xv.w * wv.w;
        }
    }
#pragma unroll
    for (int n = 0; n < NM; n++)
#pragma unroll
        for (int off = 16; off > 0; off >>= 1)
            acc[n] += __shfl_xor_sync(0xffffffffu, acc[n], off);

    if (lane == 0) {
        float l[NM], mx = -1e30f;
#pragma unroll
        for (int n = 0; n < NM; n++) { l[n] = acc[n] + Wgb[n]; mx = fmaxf(mx, l[n]); }
        float sc[NM], sum = 0.f;
#pragma unroll
        for (int n = 0; n < NM; n++) { sc[n] = expf(l[n] - mx); sum += sc[n]; }
        const float inv = 1.f / sum;
#pragma unroll
        for (int n = 0; n < NM; n++) sc[n] *= inv;

        int i0 = 0;
#pragma unroll
        for (int n = 1; n < NM; n++) if (sc[n] > sc[i0]) i0 = n;   // first max (stable)
        int i1 = (i0 == 0) ? 1 : 0;
#pragma unroll
        for (int n = 0; n < NM; n++) if (n != i0 && sc[n] > sc[i1]) i1 = n;

        const float g0 = sc[i0], g1 = sc[i1];
        const float gs = g0 + g1;
        g_ri[wid] = make_int2(i0, i1);
        g_rg[wid] = make_float2(g0 / gs, g1 / gs);
    }
}

// ---------------- recurrence: one CTA per (batch, slot); M tile in registers ----------------
// Identity used: all updates targeting slot s in a step use the SAME k/v row s,
// so duplicate routing collapses to a multiplicity scalar cf in {0,1,2}.
// Output o = sum_s w_s * (q @ M'_s), w_s = [s==0] + g0*[s==i0] + g1*[s==i1].
__global__ __launch_bounds__(256) void recur_kernel(
    const float* __restrict__ M0, float* __restrict__ out_m, int write_m)
{
    const int b = blockIdx.x / NM1;
    const int s = blockIdx.x % NM1;
    const int tid = threadIdx.x;
    const int j  = tid & 63;       // column of M owned
    const int ib = tid >> 6;       // i = ib + 4*r

    float Mreg[16];
    const float* m0p = M0 + ((size_t)(b * NM1 + s)) * HID * HID;
#pragma unroll
    for (int r = 0; r < 16; r++) Mreg[r] = m0p[(ib + 4 * r) * HID + j];

    __shared__ float kb[64], vb[64], qb[64], red[256];

    // prefetch rows for t = 0 (row index is this CTA's own slot: static)
    float stage = 0.f;
    {
        const int m = b;  // t=0
        if (tid < 64)        stage = g_Ck[(size_t)m * NKV + s * HID + tid];
        else if (tid < 128)  stage = g_Cv[(size_t)m * NKV + s * HID + (tid - 64)];
        else if (tid < 192)  stage = g_Cq[(size_t)m * HID + (tid - 128)];
    }

    for (int t = 0; t < SEQ; t++) {
        __syncthreads();   // prior step's reads of kb/vb/qb/red complete
        if (tid < 64)        kb[tid] = stage;
        else if (tid < 128)  vb[tid - 64] = stage;
        else if (tid < 192)  qb[tid - 128] = stage;
        __syncthreads();

        // prefetch t+1 into registers (hides L2 latency behind compute)
        if (t + 1 < SEQ) {
            const int m = (t + 1) * BATCH + b;
            if (tid < 64)        stage = g_Ck[(size_t)m * NKV + s * HID + tid];
            else if (tid < 128)  stage = g_Cv[(size_t)m * NKV + s * HID + (tid - 64)];
            else if (tid < 192)  stage = g_Cq[(size_t)m * HID + (tid - 128)];
        }

        const int row = t * BATCH + b;
        const int2 ii = g_ri[row];
        const float2 gg = g_rg[row];
        float cf = 0.f, w = 0.f;
        if (s == 0)    { cf += 1.f; w += 1.f; }
        if (s == ii.x) { cf += 1.f; w += gg.x; }
        if (s == ii.y) { cf += 1.f; w += gg.y; }

        if (cf != 0.f) {
            const float cv = cf * vb[j];
#pragma unroll
            for (int r = 0; r < 16; r++)
                Mreg[r] = fmaf(kb[ib + 4 * r], cv, Mreg[r]);
        }

        float part = 0.f;
#pragma unroll
        for (int r = 0; r < 16; r++)
            part = fmaf(qb[ib + 4 * r], Mreg[r], part);
        red[tid] = part;
        __syncthreads();
        if (tid < 64) {
            const float o = w * (red[tid] + red[tid + 64] + red[tid + 128] + red[tid + 192]);
            g_contrib[(size_t)row * NKV + s * HID + tid] = o;  // zeros when unselected
        }
    }

    if (write_m) {
        float* mo = out_m + ((size_t)(b * NM1 + s)) * HID * HID;
#pragma unroll
        for (int r = 0; r < 16; r++) mo[(ib + 4 * r) * HID + j] = Mreg[r];
    }
}

// ---------------- finalize: o[t,b,j] = sum_s contrib[t,b,s,j] ----------------
__global__ __launch_bounds__(256) void finalize_kernel(float* __restrict__ out)
{
    const int idx = blockIdx.x * 256 + threadIdx.x;   // < SEQ*BATCH*HID
    const int tb = idx >> 6, j = idx & 63;
    float ssum = 0.f;
#pragma unroll
    for (int u = 0; u < NM1; u++)
        ssum += g_contrib[(size_t)tb * NKV + u * HID + j];
    out[idx] = ssum;
}

// ---------------- launch ----------------
extern "C" void kernel_launch(void* const* d_in, const int* in_sizes, int n_in,
                              void* d_out, int out_size)
{
    const float* X    = (const float*)d_in[0];
    const float* M0   = (const float*)d_in[1];
    const float* Wk_w = (const float*)d_in[2];
    const float* Wk_b = (const float*)d_in[3];
    const float* Wv_w = (const float*)d_in[4];
    const float* Wv_b = (const float*)d_in[5];
    const float* Wg_w = (const float*)d_in[6];
    const float* Wg_b = (const float*)d_in[7];
    const float* Wq_w = (const float*)d_in[8];
    const float* Wq_b = (const float*)d_in[9];
    float* out = (float*)d_out;

    float *pCk, *pCv, *pCq;
    cudaGetSymbolAddress((void**)&pCk, g_Ck);
    cudaGetSymbolAddress((void**)&pCv, g_Cv);
    cudaGetSymbolAddress((void**)&pCq, g_Cq);

    gemm_tf32<<<dim3(NKV / 64, ROWS / 64), 128>>>(X, Wk_w, Wk_b, pCk, NKV);
    gemm_tf32<<<dim3(NKV / 64, ROWS / 64), 128>>>(X, Wv_w, Wv_b, pCv, NKV);
    gemm_tf32<<<dim3(1, ROWS / 64), 128>>>(X, Wq_w, Wq_b, pCq, HID);
    gate_kernel<<<ROWS / 8, 256>>>(X, Wg_w, Wg_b);

    const long OUTSEQ = (long)SEQ * BATCH * HID;                  // 524288
    const long MTOT   = (long)BATCH * NM1 * HID * HID;            // 1179648
    const int write_m = ((long)out_size >= OUTSEQ + MTOT) ? 1 : 0;

    recur_kernel<<<BATCH * NM1, 256>>>(M0, out + OUTSEQ, write_m);
    finalize_kernel<<<(int)(OUTSEQ / 256), 256>>>(out);
}

// round 4
// speedup vs baseline: 1.9232x; 1.9232x over previous
#include <cuda_runtime.h>
#include <cstdint>
#include <cstddef>

#define SEQ 256
#define BATCH 32
#define IN_DIM 1024
#define HID 64
#define NM 8
#define NM1 9
#define ROWS (SEQ*BATCH)     /* 8192 */
#define NKV (NM1*HID)        /* 576  */

// ---------------- scratch (device globals; no allocation allowed) ----------------
__device__ float  g_Xr[(size_t)ROWS * IN_DIM];     // tf32-rounded X (written by gate)
__device__ float  g_Wr[(size_t)1216 * IN_DIM];     // tf32-rounded Wk|Wv|Wq stacked
__device__ float  g_Ck[(size_t)ROWS * NKV];
__device__ float  g_Cv[(size_t)ROWS * NKV];
__device__ float  g_Cq[(size_t)ROWS * HID];
__device__ int2   g_ri[ROWS];
__device__ float2 g_rg[ROWS];
__device__ int    g_list[8][ROWS];
__device__ int    g_cnt[8];
__device__ float  g_contrib[(size_t)ROWS * NKV];

// ---------------- helpers ----------------
__device__ __forceinline__ uint32_t smem_u32(const void* p) {
    uint32_t a;
    asm("{ .reg .u64 t; cvta.to.shared.u64 t, %1; cvt.u32.u64 %0, t; }" : "=r"(a) : "l"(p));
    return a;
}
__device__ __forceinline__ void cp16(uint32_t dst, const void* src) {
    asm volatile("cp.async.cg.shared.global [%0], [%1], 16;\n" :: "r"(dst), "l"(src) : "memory");
}
__device__ __forceinline__ void cp_commit() { asm volatile("cp.async.commit_group;\n" ::: "memory"); }
template<int N> __device__ __forceinline__ void cp_wait() {
    asm volatile("cp.async.wait_group %0;\n" :: "n"(N) : "memory");
}
__device__ __forceinline__ float f2tf_rna(float f) {
    uint32_t u;
    asm("cvt.rna.tf32.f32 %0, %1;" : "=r"(u) : "f"(f));
    return __uint_as_float(u);
}
__device__ __forceinline__ void mma_tf32(float* d, const uint32_t* a, const uint32_t* b) {
    asm volatile(
        "mma.sync.aligned.m16n8k8.row.col.f32.tf32.tf32.f32 "
        "{%0,%1,%2,%3},{%4,%5,%6,%7},{%8,%9},{%0,%1,%2,%3};"
        : "+f"(d[0]), "+f"(d[1]), "+f"(d[2]), "+f"(d[3])
        : "r"(a[0]), "r"(a[1]), "r"(a[2]), "r"(a[3]), "r"(b[0]), "r"(b[1]));
}

// ---------------- tf32 pre-rounding pass (for weights) ----------------
__global__ __launch_bounds__(256) void round_copy(const float* __restrict__ src,
                                                  float* __restrict__ dst, int n4)
{
    int i = blockIdx.x * 256 + threadIdx.x;
    if (i >= n4) return;
    float4 v = ((const float4*)src)[i];
    v.x = f2tf_rna(v.x); v.y = f2tf_rna(v.y); v.z = f2tf_rna(v.z); v.w = f2tf_rna(v.w);
    ((float4*)dst)[i] = v;
}

// ---------------- gate: exact fp32 logits + softmax + stable top-2; also rounds X ----------------
__global__ __launch_bounds__(256) void gate_kernel(
    const float* __restrict__ X, const float* __restrict__ Wg,
    const float* __restrict__ Wgb)
{
    const int wid  = blockIdx.x * 8 + (threadIdx.x >> 5);
    const int lane = threadIdx.x & 31;
    const float4* x4 = (const float4*)(X + (size_t)wid * IN_DIM);
    float4* xo = (float4*)(g_Xr + (size_t)wid * IN_DIM);
    const float4* w4 = (const float4*)Wg;

    float4 xs[8];
#pragma unroll
    for (int c = 0; c < 8; c++) xs[c] = x4[c * 32 + lane];

    float acc[NM];
#pragma unroll
    for (int n = 0; n < NM; n++) acc[n] = 0.f;
#pragma unroll
    for (int c = 0; c < 8; c++) {
        const float4 xv = xs[c];
#pragma unroll
        for (int n = 0; n < NM; n++) {
            const float4 wv = w4[n * 256 + c * 32 + lane];
            acc[n] += xv.x * wv.x + xv.y * wv.y + xv.z * wv.z + xv.w * wv.w;
        }
    }
    // write rounded X (same addresses just read)
#pragma unroll
    for (int c = 0; c < 8; c++) {
        float4 v = xs[c];
        v.x = f2tf_rna(v.x); v.y = f2tf_rna(v.y); v.z = f2tf_rna(v.z); v.w = f2tf_rna(v.w);
        xo[c * 32 + lane] = v;
    }

#pragma unroll
    for (int n = 0; n < NM; n++)
#pragma unroll
        for (int off = 16; off > 0; off >>= 1)
            acc[n] += __shfl_xor_sync(0xffffffffu, acc[n], off);

    if (lane == 0) {
        float l[NM], mx = -1e30f;
#pragma unroll
        for (int n = 0; n < NM; n++) { l[n] = acc[n] + Wgb[n]; mx = fmaxf(mx, l[n]); }
        float sc[NM], sum = 0.f;
#pragma unroll
        for (int n = 0; n < NM; n++) { sc[n] = expf(l[n] - mx); sum += sc[n]; }
        const float inv = 1.f / sum;
#pragma unroll
        for (int n = 0; n < NM; n++) sc[n] *= inv;

        int i0 = 0;
#pragma unroll
        for (int n = 1; n < NM; n++) if (sc[n] > sc[i0]) i0 = n;
        int i1 = (i0 == 0) ? 1 : 0;
#pragma unroll
        for (int n = 0; n < NM; n++) if (n != i0 && sc[n] > sc[i1]) i1 = n;

        const float g0 = sc[i0], g1 = sc[i1];
        const float gs = g0 + g1;
        g_ri[wid] = make_int2(i0, i1);
        g_rg[wid] = make_float2(g0 / gs, g1 / gs);
    }
}

// ---------------- routing lists ----------------
__global__ void zero_cnt() { if (threadIdx.x < 8) g_cnt[threadIdx.x] = 0; }

__global__ __launch_bounds__(256) void listbuild()
{
    const int row = blockIdx.x * 256 + threadIdx.x;
    const int tid = threadIdx.x;
    __shared__ int scnt[8], sbase[8];
    if (tid < 8) scnt[tid] = 0;
    __syncthreads();
    const int2 ii = g_ri[row];
    int p0 = -1, p1 = -1;
    if (ii.x > 0) p0 = atomicAdd(&scnt[ii.x], 1);
    if (ii.y > 0) p1 = atomicAdd(&scnt[ii.y], 1);
    __syncthreads();
    if (tid < 8 && scnt[tid] > 0) sbase[tid] = atomicAdd(&g_cnt[tid], scnt[tid]);
    __syncthreads();
    if (p0 >= 0) g_list[ii.x][sbase[ii.x] + p0] = row;
    if (p1 >= 0) g_list[ii.y][sbase[ii.y] + p1] = row;
}

// ---------------- gathered tf32 mma.sync GEMM ----------------
// job 0..7: slot s: rows = (s==0 ? all : list[s]); B = [Wk slot s (64) | Wv slot s (64)] -> N=128
// job 8:    q:      rows = all; B = Wq (64 rows, wrapped) -> store only cols<64
// CTA: 128 rows x 128 cols, K-stage 32, 3-stage cp.async, 8 warps (2M x 4N), warp 64x32.
#define STGF 9216              /* (128+128)*36 floats per stage */
#define GSMEM (3*STGF*4)       /* 110592 bytes */

__global__ __launch_bounds__(256, 2) void gemm_mma(
    const float* __restrict__ Wk_b, const float* __restrict__ Wv_b,
    const float* __restrict__ Wq_b)
{
    extern __shared__ float smf[];
    const int tid  = threadIdx.x;
    const int lane = tid & 31;
    const int warp = tid >> 5;
    const int wm = (warp >> 2) * 64;          // 0 or 64
    const int wn = (warp & 3) * 32;           // 0,32,64,96
    const int job = blockIdx.y;               // 0..8
    const int m0 = blockIdx.x * 128;
    const bool isq = (job == 8);
    const int cnt = (job == 0 || isq) ? ROWS : g_cnt[job];
    if (m0 >= cnt) return;

    __shared__ int slist[128];
    if (tid < 128) {
        int idx = m0 + tid;
        int cl = idx < cnt ? idx : cnt - 1;
        slist[tid] = (job == 0 || isq) ? idx : g_list[job][cl];
    }
    __syncthreads();

    // per-thread cp.async chunk descriptors (4 A-chunks + 4 B-chunks)
    uint32_t aoff[4], asmo[4], boff[4], bsmo[4];
    const uint32_t sbase = smem_u32(smf);
#pragma unroll
    for (int u = 0; u < 4; u++) {
        const int id = u * 256 + tid;
        const int row = id >> 3, c16 = id & 7;
        aoff[u] = (uint32_t)slist[row] * IN_DIM + c16 * 4;
        asmo[u] = (uint32_t)(row * 36 + c16 * 4) * 4;
        int br;
        if (!isq) br = (row < 64) ? job * 64 + row : 576 + job * 64 + (row - 64);
        else      br = 1152 + (row & 63);
        boff[u] = (uint32_t)br * IN_DIM + c16 * 4;
        bsmo[u] = (uint32_t)(128 * 36 + row * 36 + c16 * 4) * 4;
    }

    auto loadst = [&](int j) {
        const uint32_t st = sbase + (uint32_t)(j % 3) * (STGF * 4);
        const uint32_t k0 = (uint32_t)j * 32;
#pragma unroll
        for (int u = 0; u < 4; u++) cp16(st + asmo[u], g_Xr + aoff[u] + k0);
#pragma unroll
        for (int u = 0; u < 4; u++) cp16(st + bsmo[u], g_Wr + boff[u] + k0);
    };

    loadst(0); cp_commit();
    loadst(1); cp_commit();

    float acc[4][4][4];
#pragma unroll
    for (int mt = 0; mt < 4; mt++)
#pragma unroll
        for (int nt = 0; nt < 4; nt++)
#pragma unroll
            for (int i = 0; i < 4; i++) acc[mt][nt][i] = 0.f;

    for (int i = 0; i < 32; i++) {
        cp_wait<1>();
        __syncthreads();
        if (i + 2 < 32) loadst(i + 2);
        cp_commit();

        const float* As = smf + (i % 3) * STGF;
        const float* Bs = As + 128 * 36;
#pragma unroll
        for (int ks = 0; ks < 4; ks++) {
            const int kk = ks * 8 + (lane & 3);
            uint32_t af[4][4], bf[4][2];
#pragma unroll
            for (int mt = 0; mt < 4; mt++) {
                const int r = wm + mt * 16 + (lane >> 2);
                af[mt][0] = __float_as_uint(As[r * 36 + kk]);
                af[mt][1] = __float_as_uint(As[(r + 8) * 36 + kk]);
                af[mt][2] = __float_as_uint(As[r * 36 + kk + 4]);
                af[mt][3] = __float_as_uint(As[(r + 8) * 36 + kk + 4]);
            }
#pragma unroll
            for (int nt = 0; nt < 4; nt++) {
                const int n = wn + nt * 8 + (lane >> 2);
                bf[nt][0] = __float_as_uint(Bs[n * 36 + kk]);
                bf[nt][1] = __float_as_uint(Bs[n * 36 + kk + 4]);
            }
#pragma unroll
            for (int mt = 0; mt < 4; mt++)
#pragma unroll
                for (int nt = 0; nt < 4; nt++)
                    mma_tf32(acc[mt][nt], af[mt], bf[nt]);
        }
    }

    // epilogue
    if (isq && wn >= 64) return;
#pragma unroll
    for (int mt = 0; mt < 4; mt++) {
#pragma unroll
        for (int half = 0; half < 2; half++) {
            const int lr = wm + mt * 16 + (lane >> 2) + half * 8;
            if (m0 + lr >= cnt) continue;
            const int row = slist[lr];
#pragma unroll
            for (int nt = 0; nt < 4; nt++) {
                const int col = wn + nt * 8 + (lane & 3) * 2;
                const float a0 = acc[mt][nt][half * 2 + 0];
                const float a1 = acc[mt][nt][half * 2 + 1];
                if (isq) {
                    float2 v = { a0 + Wq_b[col], a1 + Wq_b[col + 1] };
                    *(float2*)(g_Cq + (size_t)row * HID + col) = v;
                } else if (col < 64) {
                    float2 v = { a0 + Wk_b[job * 64 + col], a1 + Wk_b[job * 64 + col + 1] };
                    *(float2*)(g_Ck + (size_t)row * NKV + job * 64 + col) = v;
                } else {
                    const int c = col - 64;
                    float2 v = { a0 + Wv_b[job * 64 + c], a1 + Wv_b[job * 64 + c + 1] };
                    *(float2*)(g_Cv + (size_t)row * NKV + job * 64 + c) = v;
                }
            }
        }
    }
}

// ---------------- recurrence: one CTA per (batch, slot); M tile in registers ----------------
__global__ __launch_bounds__(256) void recur_kernel(
    const float* __restrict__ M0, float* __restrict__ out_m, int write_m)
{
    const int b = blockIdx.x / NM1;
    const int s = blockIdx.x % NM1;
    const int tid = threadIdx.x;
    const int j  = tid & 63;
    const int ib = tid >> 6;

    float Mreg[16];
    const float* m0p = M0 + ((size_t)(b * NM1 + s)) * HID * HID;
#pragma unroll
    for (int r = 0; r < 16; r++) Mreg[r] = m0p[(ib + 4 * r) * HID + j];

    __shared__ float kb[64], vb[64], qb[64], red[256];

    float stage = 0.f;
    {
        const int m = b;
        if (tid < 64)        stage = g_Ck[(size_t)m * NKV + s * HID + tid];
        else if (tid < 128)  stage = g_Cv[(size_t)m * NKV + s * HID + (tid - 64)];
        else if (tid < 192)  stage = g_Cq[(size_t)m * HID + (tid - 128)];
    }

    for (int t = 0; t < SEQ; t++) {
        __syncthreads();
        if (tid < 64)        kb[tid] = stage;
        else if (tid < 128)  vb[tid - 64] = stage;
        else if (tid < 192)  qb[tid - 128] = stage;
        __syncthreads();

        if (t + 1 < SEQ) {
            const int m = (t + 1) * BATCH + b;
            if (tid < 64)        stage = g_Ck[(size_t)m * NKV + s * HID + tid];
            else if (tid < 128)  stage = g_Cv[(size_t)m * NKV + s * HID + (tid - 64)];
            else if (tid < 192)  stage = g_Cq[(size_t)m * HID + (tid - 128)];
        }

        const int row = t * BATCH + b;
        const int2 ii = g_ri[row];
        const float2 gg = g_rg[row];
        float cf = 0.f, w = 0.f;
        if (s == 0)    { cf += 1.f; w += 1.f; }
        if (s == ii.x) { cf += 1.f; w += gg.x; }
        if (s == ii.y) { cf += 1.f; w += gg.y; }

        if (cf != 0.f) {
            const float cv = cf * vb[j];
#pragma unroll
            for (int r = 0; r < 16; r++)
                Mreg[r] = fmaf(kb[ib + 4 * r], cv, Mreg[r]);
        }

        float part = 0.f;
#pragma unroll
        for (int r = 0; r < 16; r++)
            part = fmaf(qb[ib + 4 * r], Mreg[r], part);
        red[tid] = part;
        __syncthreads();
        if (tid < 64) {
            const float o = w * (red[tid] + red[tid + 64] + red[tid + 128] + red[tid + 192]);
            g_contrib[(size_t)row * NKV + s * HID + tid] = o;
        }
    }

    if (write_m) {
        float* mo = out_m + ((size_t)(b * NM1 + s)) * HID * HID;
#pragma unroll
        for (int r = 0; r < 16; r++) mo[(ib + 4 * r) * HID + j] = Mreg[r];
    }
}

// ---------------- finalize: o[t,b,j] = sum_s contrib[t,b,s,j] ----------------
__global__ __launch_bounds__(256) void finalize_kernel(float* __restrict__ out)
{
    const int idx = blockIdx.x * 256 + threadIdx.x;
    const int tb = idx >> 6, j = idx & 63;
    float ssum = 0.f;
#pragma unroll
    for (int u = 0; u < NM1; u++)
        ssum += g_contrib[(size_t)tb * NKV + u * HID + j];
    out[idx] = ssum;
}

// ---------------- launch ----------------
extern "C" void kernel_launch(void* const* d_in, const int* in_sizes, int n_in,
                              void* d_out, int out_size)
{
    const float* X    = (const float*)d_in[0];
    const float* M0   = (const float*)d_in[1];
    const float* Wk_w = (const float*)d_in[2];
    const float* Wk_b = (const float*)d_in[3];
    const float* Wv_w = (const float*)d_in[4];
    const float* Wv_b = (const float*)d_in[5];
    const float* Wg_w = (const float*)d_in[6];
    const float* Wg_b = (const float*)d_in[7];
    const float* Wq_w = (const float*)d_in[8];
    const float* Wq_b = (const float*)d_in[9];
    float* out = (float*)d_out;

    float* pWr;
    cudaGetSymbolAddress((void**)&pWr, g_Wr);

    // round stacked weights to tf32 (independent of gate)
    {
        const int nk4 = NKV * IN_DIM / 4;                   // 147456
        round_copy<<<(nk4 + 255) / 256, 256>>>(Wk_w, pWr, nk4);
        round_copy<<<(nk4 + 255) / 256, 256>>>(Wv_w, pWr + (size_t)576 * IN_DIM, nk4);
        const int nq4 = HID * IN_DIM / 4;                   // 16384
        round_copy<<<(nq4 + 255) / 256, 256>>>(Wq_w, pWr + (size_t)1152 * IN_DIM, nq4);
    }

    gate_kernel<<<ROWS / 8, 256>>>(X, Wg_w, Wg_b);          // also writes g_Xr
    zero_cnt<<<1, 32>>>();
    listbuild<<<ROWS / 256, 256>>>();

    cudaFuncSetAttribute(gemm_mma, cudaFuncAttributeMaxDynamicSharedMemorySize, GSMEM);
    gemm_mma<<<dim3(64, 9), 256, GSMEM>>>(Wk_b, Wv_b, Wq_b);

    const long OUTSEQ = (long)SEQ * BATCH * HID;            // 524288
    const long MTOT   = (long)BATCH * NM1 * HID * HID;      // 1179648
    const int write_m = ((long)out_size >= OUTSEQ + MTOT) ? 1 : 0;

    recur_kernel<<<BATCH * NM1, 256>>>(M0, out + OUTSEQ, write_m);
    finalize_kernel<<<(int)(OUTSEQ / 256), 256>>>(out);
}

// round 5
// speedup vs baseline: 2.2914x; 1.1914x over previous
#include <cuda_runtime.h>
#include <cstdint>
#include <cstddef>

#define SEQ 256
#define BATCH 32
#define IN_DIM 1024
#define HID 64
#define NM 8
#define NM1 9
#define ROWS (SEQ*BATCH)     /* 8192 */
#define NKV (NM1*HID)        /* 576  */

// ---------------- scratch (device globals; no allocation allowed) ----------------
__device__ float  g_Xr[(size_t)ROWS * IN_DIM];     // tf32-rounded, k-pair-permuted X
__device__ float  g_Wr[(size_t)1216 * IN_DIM];     // tf32-rounded, permuted Wk|Wv|Wq
__device__ float  g_Ck[(size_t)ROWS * NKV];
__device__ float  g_Cv[(size_t)ROWS * NKV];
__device__ float  g_Cq[(size_t)ROWS * HID];
__device__ int2   g_ri[ROWS];
__device__ int4   g_meta[ROWS];                    // {i0, i1, bits(g0), bits(g1)}
__device__ int    g_list[8][ROWS];
__device__ int    g_cnt[8];
__device__ float  g_c3[(size_t)ROWS * 3 * HID];    // compact contribs

// ---------------- helpers ----------------
__device__ __forceinline__ uint32_t smem_u32(const void* p) {
    uint32_t a;
    asm("{ .reg .u64 t; cvta.to.shared.u64 t, %1; cvt.u32.u64 %0, t; }" : "=r"(a) : "l"(p));
    return a;
}
__device__ __forceinline__ void cp16(uint32_t dst, const void* src) {
    asm volatile("cp.async.cg.shared.global [%0], [%1], 16;\n" :: "r"(dst), "l"(src) : "memory");
}
__device__ __forceinline__ void cp_commit() { asm volatile("cp.async.commit_group;\n" ::: "memory"); }
template<int N> __device__ __forceinline__ void cp_wait() {
    asm volatile("cp.async.wait_group %0;\n" :: "n"(N) : "memory");
}
__device__ __forceinline__ float f2tf_rna(float f) {
    uint32_t u;
    asm("cvt.rna.tf32.f32 %0, %1;" : "=r"(u) : "f"(f));
    return __uint_as_float(u);
}
__device__ __forceinline__ void mma_tf32(float* d, const uint32_t* a, const uint32_t* b) {
    asm volatile(
        "mma.sync.aligned.m16n8k8.row.col.f32.tf32.tf32.f32 "
        "{%0,%1,%2,%3},{%4,%5,%6,%7},{%8,%9},{%0,%1,%2,%3};"
        : "+f"(d[0]), "+f"(d[1]), "+f"(d[2]), "+f"(d[3])
        : "r"(a[0]), "r"(a[1]), "r"(a[2]), "r"(a[3]), "r"(b[0]), "r"(b[1]));
}

// ---------------- weights: tf32 round + k-pair permute ----------------
// within each 8-float k-block: dst position p holds src sigma(p), sigma=[0,4,1,5,2,6,3,7]
__global__ __launch_bounds__(256) void round_perm(const float* __restrict__ src,
                                                  float* __restrict__ dst, int nblk)
{
    int i = blockIdx.x * 256 + threadIdx.x;
    if (i >= nblk) return;
    const float4* s4 = (const float4*)src;
    float4* d4 = (float4*)dst;
    float4 a = s4[2 * i], b = s4[2 * i + 1];
    float4 o0 = { f2tf_rna(a.x), f2tf_rna(b.x), f2tf_rna(a.y), f2tf_rna(b.y) };
    float4 o1 = { f2tf_rna(a.z), f2tf_rna(b.z), f2tf_rna(a.w), f2tf_rna(b.w) };
    d4[2 * i] = o0;
    d4[2 * i + 1] = o1;
}

// ---------------- gate: exact fp32 logits + softmax + top-2; writes permuted Xr ----------------
__global__ __launch_bounds__(256) void gate_kernel(
    const float* __restrict__ X, const float* __restrict__ Wg,
    const float* __restrict__ Wgb)
{
    const int wid  = blockIdx.x * 8 + (threadIdx.x >> 5);
    const int lane = threadIdx.x & 31;
    const float4* x4 = (const float4*)(X + (size_t)wid * IN_DIM);
    float4* xo = (float4*)(g_Xr + (size_t)wid * IN_DIM);
    const float4* w4 = (const float4*)Wg;

    float acc[NM];
#pragma unroll
    for (int n = 0; n < NM; n++) acc[n] = 0.f;

#pragma unroll
    for (int c = 0; c < 4; c++) {
        const int blk = c * 32 + lane;          // 8-float block index (0..127)
        const float4 a = x4[2 * blk];
        const float4 b = x4[2 * blk + 1];
#pragma unroll
        for (int n = 0; n < NM; n++) {
            const float4 wa = w4[n * 256 + 2 * blk];
            const float4 wb = w4[n * 256 + 2 * blk + 1];
            acc[n] += a.x * wa.x + a.y * wa.y + a.z * wa.z + a.w * wa.w
                    + b.x * wb.x + b.y * wb.y + b.z * wb.z + b.w * wb.w;
        }
        float4 o0 = { f2tf_rna(a.x), f2tf_rna(b.x), f2tf_rna(a.y), f2tf_rna(b.y) };
        float4 o1 = { f2tf_rna(a.z), f2tf_rna(b.z), f2tf_rna(a.w), f2tf_rna(b.w) };
        xo[2 * blk] = o0;
        xo[2 * blk + 1] = o1;
    }

#pragma unroll
    for (int n = 0; n < NM; n++)
#pragma unroll
        for (int off = 16; off > 0; off >>= 1)
            acc[n] += __shfl_xor_sync(0xffffffffu, acc[n], off);

    if (lane == 0) {
        float l[NM], mx = -1e30f;
#pragma unroll
        for (int n = 0; n < NM; n++) { l[n] = acc[n] + Wgb[n]; mx = fmaxf(mx, l[n]); }
        float sc[NM], sum = 0.f;
#pragma unroll
        for (int n = 0; n < NM; n++) { sc[n] = expf(l[n] - mx); sum += sc[n]; }
        const float inv = 1.f / sum;
#pragma unroll
        for (int n = 0; n < NM; n++) sc[n] *= inv;

        int i0 = 0;
#pragma unroll
        for (int n = 1; n < NM; n++) if (sc[n] > sc[i0]) i0 = n;
        int i1 = (i0 == 0) ? 1 : 0;
#pragma unroll
        for (int n = 0; n < NM; n++) if (n != i0 && sc[n] > sc[i1]) i1 = n;

        const float g0 = sc[i0], g1 = sc[i1];
        const float gs = g0 + g1;
        g_ri[wid] = make_int2(i0, i1);
        g_meta[wid] = make_int4(i0, i1, __float_as_int(g0 / gs), __float_as_int(g1 / gs));
    }
}

// ---------------- routing lists ----------------
__global__ void zero_cnt() { if (threadIdx.x < 8) g_cnt[threadIdx.x] = 0; }

__global__ __launch_bounds__(256) void listbuild()
{
    const int row = blockIdx.x * 256 + threadIdx.x;
    const int tid = threadIdx.x;
    __shared__ int scnt[8], sbase[8];
    if (tid < 8) scnt[tid] = 0;
    __syncthreads();
    const int2 ii = g_ri[row];
    int p0 = -1, p1 = -1;
    if (ii.x > 0) p0 = atomicAdd(&scnt[ii.x], 1);
    if (ii.y > 0) p1 = atomicAdd(&scnt[ii.y], 1);
    __syncthreads();
    if (tid < 8 && scnt[tid] > 0) sbase[tid] = atomicAdd(&g_cnt[tid], scnt[tid]);
    __syncthreads();
    if (p0 >= 0) g_list[ii.x][sbase[ii.x] + p0] = row;
    if (p1 >= 0) g_list[ii.y][sbase[ii.y] + p1] = row;
}

// ---------------- gathered tf32 mma.sync GEMM (LDS.64 fragments) ----------------
#define STGF 9216              /* (128+128)*36 floats per stage */
#define GSMEM (3*STGF*4)       /* 110592 bytes */

__global__ __launch_bounds__(256, 2) void gemm_mma(
    const float* __restrict__ Wk_b, const float* __restrict__ Wv_b,
    const float* __restrict__ Wq_b)
{
    extern __shared__ float smf[];
    const int tid  = threadIdx.x;
    const int lane = tid & 31;
    const int warp = tid >> 5;
    const int wm = (warp >> 2) * 64;          // 0 or 64
    const int wn = (warp & 3) * 32;           // 0,32,64,96
    const int job = blockIdx.y;               // 0..8
    const int m0 = blockIdx.x * 128;
    const bool isq = (job == 8);
    const int cnt = (job == 0 || isq) ? ROWS : g_cnt[job];
    if (m0 >= cnt) return;

    __shared__ int slist[128];
    if (tid < 128) {
        int idx = m0 + tid;
        int cl = idx < cnt ? idx : cnt - 1;
        slist[tid] = (job == 0 || isq) ? idx : g_list[job][cl];
    }
    __syncthreads();

    uint32_t aoff[4], asmo[4], boff[4], bsmo[4];
    const uint32_t sbase = smem_u32(smf);
#pragma unroll
    for (int u = 0; u < 4; u++) {
        const int id = u * 256 + tid;
        const int row = id >> 3, c16 = id & 7;
        aoff[u] = (uint32_t)slist[row] * IN_DIM + c16 * 4;
        asmo[u] = (uint32_t)(row * 36 + c16 * 4) * 4;
        int br;
        if (!isq) br = (row < 64) ? job * 64 + row : 576 + job * 64 + (row - 64);
        else      br = 1152 + (row & 63);
        boff[u] = (uint32_t)br * IN_DIM + c16 * 4;
        bsmo[u] = (uint32_t)(128 * 36 + row * 36 + c16 * 4) * 4;
    }

    auto loadst = [&](int j) {
        const uint32_t st = sbase + (uint32_t)(j % 3) * (STGF * 4);
        const uint32_t k0 = (uint32_t)j * 32;
#pragma unroll
        for (int u = 0; u < 4; u++) cp16(st + asmo[u], g_Xr + aoff[u] + k0);
#pragma unroll
        for (int u = 0; u < 4; u++) cp16(st + bsmo[u], g_Wr + boff[u] + k0);
    };

    loadst(0); cp_commit();
    loadst(1); cp_commit();

    float acc[4][4][4];
#pragma unroll
    for (int mt = 0; mt < 4; mt++)
#pragma unroll
        for (int nt = 0; nt < 4; nt++)
#pragma unroll
            for (int i = 0; i < 4; i++) acc[mt][nt][i] = 0.f;

    const int c4 = lane & 3;
    const int r0 = lane >> 2;

    for (int i = 0; i < 32; i++) {
        cp_wait<1>();
        __syncthreads();
        if (i + 2 < 32) loadst(i + 2);
        cp_commit();

        const float2* As2 = (const float2*)(smf + (i % 3) * STGF);
        const float2* Bs2 = As2 + 128 * 18;
#pragma unroll
        for (int ks = 0; ks < 4; ks++) {
            uint32_t af[4][4], bf[4][2];
#pragma unroll
            for (int mt = 0; mt < 4; mt++) {
                const int ra = (wm + mt * 16 + r0) * 18 + ks * 4 + c4;
                const float2 pr  = As2[ra];
                const float2 pr8 = As2[ra + 8 * 18];
                af[mt][0] = __float_as_uint(pr.x);
                af[mt][1] = __float_as_uint(pr8.x);
                af[mt][2] = __float_as_uint(pr.y);
                af[mt][3] = __float_as_uint(pr8.y);
            }
#pragma unroll
            for (int nt = 0; nt < 4; nt++) {
                const int nb = (wn + nt * 8 + r0) * 18 + ks * 4 + c4;
                const float2 bv = Bs2[nb];
                bf[nt][0] = __float_as_uint(bv.x);
                bf[nt][1] = __float_as_uint(bv.y);
            }
#pragma unroll
            for (int mt = 0; mt < 4; mt++)
#pragma unroll
                for (int nt = 0; nt < 4; nt++)
                    mma_tf32(acc[mt][nt], af[mt], bf[nt]);
        }
    }

    // epilogue
    if (isq && wn >= 64) return;
#pragma unroll
    for (int mt = 0; mt < 4; mt++) {
#pragma unroll
        for (int half = 0; half < 2; half++) {
            const int lr = wm + mt * 16 + r0 + half * 8;
            if (m0 + lr >= cnt) continue;
            const int row = slist[lr];
#pragma unroll
            for (int nt = 0; nt < 4; nt++) {
                const int col = wn + nt * 8 + c4 * 2;
                const float a0 = acc[mt][nt][half * 2 + 0];
                const float a1 = acc[mt][nt][half * 2 + 1];
                if (isq) {
                    float2 v = { a0 + Wq_b[col], a1 + Wq_b[col + 1] };
                    *(float2*)(g_Cq + (size_t)row * HID + col) = v;
                } else if (col < 64) {
                    float2 v = { a0 + Wk_b[job * 64 + col], a1 + Wk_b[job * 64 + col + 1] };
                    *(float2*)(g_Ck + (size_t)row * NKV + job * 64 + col) = v;
                } else {
                    const int c = col - 64;
                    float2 v = { a0 + Wv_b[job * 64 + c], a1 + Wv_b[job * 64 + c + 1] };
                    *(float2*)(g_Cv + (size_t)row * NKV + job * 64 + c) = v;
                }
            }
        }
    }
}

// ---------------- recurrence: 6-stage cp.async ring, 1 barrier/step ----------------
// thread mapping: j = tid>>2 (column), ib = tid&3; Mreg[r] = M[ib+4r][j]
#define RSTG 208   /* floats per stage: k64 | v64 | q64 | meta4 | pad */

__global__ __launch_bounds__(256) void recur_kernel(
    const float* __restrict__ M0, float* __restrict__ out_m, int write_m)
{
    const int b = blockIdx.x / NM1;
    const int s = blockIdx.x % NM1;
    const int tid = threadIdx.x;
    const int j  = tid >> 2;
    const int ib = tid & 3;

    float Mreg[16];
    const float* m0p = M0 + ((size_t)(b * NM1 + s)) * HID * HID;
#pragma unroll
    for (int r = 0; r < 16; r++) Mreg[r] = m0p[(ib + 4 * r) * HID + j];

    __shared__ float srf[6 * RSTG];
    const uint32_t sring = smem_u32(srf);

    auto load_stage = [&](int t) {
        const uint32_t st = sring + (uint32_t)(t % 6) * (RSTG * 4);
        const int m = t * BATCH + b;
        if (tid < 16)       cp16(st + tid * 16,              g_Ck + (size_t)m * NKV + s * HID + tid * 4);
        else if (tid < 32)  cp16(st + 256 + (tid - 16) * 16, g_Cv + (size_t)m * NKV + s * HID + (tid - 16) * 4);
        else if (tid < 48)  cp16(st + 512 + (tid - 32) * 16, g_Cq + (size_t)m * HID + (tid - 32) * 4);
        else if (tid == 48) cp16(st + 768,                   &g_meta[m]);
    };

#pragma unroll
    for (int t = 0; t < 5; t++) { load_stage(t); cp_commit(); }

    for (int t = 0; t < SEQ; t++) {
        cp_wait<4>();
        __syncthreads();
        if (t + 5 < SEQ) load_stage(t + 5);
        cp_commit();

        const float* st = srf + (t % 6) * RSTG;
        const int* sti = (const int*)st;
        const int i0 = sti[192], i1 = sti[193];
        const float gg0 = st[194], gg1 = st[195];

        float cf = 0.f, w = 0.f;
        if (s == 0)  { cf += 1.f; w += 1.f; }
        if (s == i0) { cf += 1.f; w += gg0; }
        if (s == i1) { cf += 1.f; w += gg1; }

        const float vj = st[64 + j];
        if (cf != 0.f) {
            const float cv = cf * vj;
#pragma unroll
            for (int r = 0; r < 16; r++)
                Mreg[r] = fmaf(st[ib + 4 * r], cv, Mreg[r]);
        }

        float p0 = 0.f, p1 = 0.f;
#pragma unroll
        for (int r = 0; r < 8; r++) {
            p0 = fmaf(st[128 + ib + 8 * r],     Mreg[2 * r],     p0);
            p1 = fmaf(st[128 + ib + 8 * r + 4], Mreg[2 * r + 1], p1);
        }
        float p = p0 + p1;
        p += __shfl_xor_sync(0xffffffffu, p, 1);
        p += __shfl_xor_sync(0xffffffffu, p, 2);

        if (ib == 0) {
            const int row = t * BATCH + b;
            const int pos = (s == 0) ? 0 : (s == i0) ? 1 : (s == i1) ? 2 : -1;
            if (pos >= 0) g_c3[((size_t)row * 3 + pos) * HID + j] = w * p;
            if (s == 0) {
                if (i0 == 0) g_c3[((size_t)row * 3 + 1) * HID + j] = 0.f;
                if (i1 == 0) g_c3[((size_t)row * 3 + 2) * HID + j] = 0.f;
            }
        }
    }

    if (write_m) {
        float* mo = out_m + ((size_t)(b * NM1 + s)) * HID * HID;
#pragma unroll
        for (int r = 0; r < 16; r++) mo[(ib + 4 * r) * HID + j] = Mreg[r];
    }
}

// ---------------- finalize: o[t,b,j] = sum of 3 compact contribs ----------------
__global__ __launch_bounds__(256) void finalize_kernel(float* __restrict__ out)
{
    const int idx = blockIdx.x * 256 + threadIdx.x;
    const int tb = idx >> 6, j = idx & 63;
    out[idx] = g_c3[((size_t)tb * 3 + 0) * HID + j]
             + g_c3[((size_t)tb * 3 + 1) * HID + j]
             + g_c3[((size_t)tb * 3 + 2) * HID + j];
}

// ---------------- launch ----------------
extern "C" void kernel_launch(void* const* d_in, const int* in_sizes, int n_in,
                              void* d_out, int out_size)
{
    const float* X    = (const float*)d_in[0];
    const float* M0   = (const float*)d_in[1];
    const float* Wk_w = (const float*)d_in[2];
    const float* Wk_b = (const float*)d_in[3];
    const float* Wv_w = (const float*)d_in[4];
    const float* Wv_b = (const float*)d_in[5];
    const float* Wg_w = (const float*)d_in[6];
    const float* Wg_b = (const float*)d_in[7];
    const float* Wq_w = (const float*)d_in[8];
    const float* Wq_b = (const float*)d_in[9];
    float* out = (float*)d_out;

    float* pWr;
    cudaGetSymbolAddress((void**)&pWr, g_Wr);

    // round+permute stacked weights
    {
        const int nkb = NKV * IN_DIM / 8;                   // 73728 blocks
        round_perm<<<(nkb + 255) / 256, 256>>>(Wk_w, pWr, nkb);
        round_perm<<<(nkb + 255) / 256, 256>>>(Wv_w, pWr + (size_t)576 * IN_DIM, nkb);
        const int nqb = HID * IN_DIM / 8;                   // 8192 blocks
        round_perm<<<(nqb + 255) / 256, 256>>>(Wq_w, pWr + (size_t)1152 * IN_DIM, nqb);
    }

    gate_kernel<<<ROWS / 8, 256>>>(X, Wg_w, Wg_b);          // also writes permuted g_Xr + meta
    zero_cnt<<<1, 32>>>();
    listbuild<<<ROWS / 256, 256>>>();

    cudaFuncSetAttribute(gemm_mma, cudaFuncAttributeMaxDynamicSharedMemorySize, GSMEM);
    gemm_mma<<<dim3(64, 9), 256, GSMEM>>>(Wk_b, Wv_b, Wq_b);

    const long OUTSEQ = (long)SEQ * BATCH * HID;            // 524288
    const long MTOT   = (long)BATCH * NM1 * HID * HID;      // 1179648
    const int write_m = ((long)out_size >= OUTSEQ + MTOT) ? 1 : 0;

    recur_kernel<<<BATCH * NM1, 256>>>(M0, out + OUTSEQ, write_m);
    finalize_kernel<<<(int)(OUTSEQ / 256), 256>>>(out);
}